// round 11
// baseline (speedup 1.0000x reference)
#include <cuda_runtime.h>
#include <cstdint>
#include <climits>

// ColBERT MaxSim on GB300 (sm_103): int8 mma.sync (m16n8k32) with factorable scales.
// qs: (64, 32, 128) fp32 ; ps: (64, 1024, 128) fp32 ; out: (64, 64) fp32
// out[b,c] = sum_n max_s dot(qs[b,n,:], ps[c,s,:])
//
// Quantization: qs per-row scale (factors out of max exactly); ps per-(doc,
// 64-token group) scale so max over tokens in a group is an integer max.

#define NQ       64
#define TQ       32
#define ND       64
#define TS       1024
#define DIM      128
#define G_Q      4
#define THREADS  128
#define SN       128                   // doc tokens per chunk
#define NCHUNK   (TS / SN)             // 8
#define ROWB     128                   // bytes per token row (int8)
#define BUFB     (SN * ROWB)           // 16 KB per buffer
#define NGRP     16                    // 64-token scale groups per doc

// int8 ps scratch (u32 view) + group scales (device-global; allocation-free)
__device__ unsigned scratch_i8[(size_t)ND * TS * DIM / 4];   // 8 MB
__device__ float    sp_scale[ND * NGRP];                     // per-group dequant scale

// ---- prepass: per (doc, 64-token group) abs-max + int8 quantize ----
__global__ void quant_ps_kernel(const float4* __restrict__ src) {
    __shared__ float wmax[8];
    const int blk  = blockIdx.x;          // doc*16 + grp
    const int tid  = threadIdx.x;         // 256 threads
    const int base = blk * 2048;          // float4 units (64 tok * 32 f4)

    float4 v[8];
    float mx = 0.f;
    #pragma unroll
    for (int i = 0; i < 8; i++) {
        v[i] = src[base + i * 256 + tid];
        mx = fmaxf(mx, fmaxf(fmaxf(fabsf(v[i].x), fabsf(v[i].y)),
                             fmaxf(fabsf(v[i].z), fabsf(v[i].w))));
    }
    #pragma unroll
    for (int off = 16; off >= 1; off >>= 1)
        mx = fmaxf(mx, __shfl_xor_sync(0xffffffffu, mx, off));
    if ((tid & 31) == 0) wmax[tid >> 5] = mx;
    __syncthreads();
    mx = wmax[0];
    #pragma unroll
    for (int j = 1; j < 8; j++) mx = fmaxf(mx, wmax[j]);

    const float qm = 127.0f / mx;
    #pragma unroll
    for (int i = 0; i < 8; i++) {
        int i0 = __float2int_rn(v[i].x * qm);
        int i1 = __float2int_rn(v[i].y * qm);
        int i2 = __float2int_rn(v[i].z * qm);
        int i3 = __float2int_rn(v[i].w * qm);
        unsigned p = (i0 & 0xFF) | ((i1 & 0xFF) << 8) |
                     ((i2 & 0xFF) << 16) | ((unsigned)(i3 & 0xFF) << 24);
        scratch_i8[base + i * 256 + tid] = p;
    }
    if (tid == 0) sp_scale[blk] = mx * (1.0f / 127.0f);
}

__device__ __forceinline__ uint32_t smem_u32(const void* p) {
    uint32_t a;
    asm("{ .reg .u64 t; cvta.to.shared.u64 t, %1; cvt.u32.u64 %0, t; }" : "=r"(a) : "l"(p));
    return a;
}
// m16n8k32 s8 mma, s32 accumulate
__device__ __forceinline__ void mma_s8(int c[4],
                                       unsigned a0, unsigned a1, unsigned a2, unsigned a3,
                                       unsigned b0, unsigned b1) {
    asm volatile(
        "mma.sync.aligned.m16n8k32.row.col.s32.s8.s8.s32 "
        "{%0,%1,%2,%3}, {%4,%5,%6,%7}, {%8,%9}, {%0,%1,%2,%3};\n"
        : "+r"(c[0]), "+r"(c[1]), "+r"(c[2]), "+r"(c[3])
        : "r"(a0), "r"(a1), "r"(a2), "r"(a3), "r"(b0), "r"(b1));
}

__global__ __launch_bounds__(THREADS, 4)
void colbert_kernel(const float* __restrict__ qs, float* __restrict__ out) {
    __shared__ __align__(1024) char Bs[2 * BUFB];

    const int tid   = threadIdx.x;
    const int w     = tid >> 5;           // warp = query within group
    const int lane  = tid & 31;
    const int g     = lane >> 2;
    const int t     = lane & 3;
    const int c_doc = blockIdx.x;
    const int qg    = blockIdx.y;
    const uint32_t sb = smem_u32(Bs);

    const uint4* gsrc = reinterpret_cast<const uint4*>(scratch_i8) + (size_t)c_doc * TS * ROWB / 16;

    // ---- prologue: async-copy chunk 0 (XOR-swizzled 16B units) ----
    #pragma unroll
    for (int j = 0; j < 8; j++) {
        int f = j * THREADS + tid;        // 1024 units per chunk
        int r = f >> 3, u = f & 7;        // 8 units per 128B row
        uint32_t dst = sb + r * ROWB + ((u ^ (r & 7)) << 4);
        asm volatile("cp.async.cg.shared.global [%0], [%1], 16;\n" :: "r"(dst), "l"(gsrc + f));
    }
    asm volatile("cp.async.commit_group;\n");

    // ---- A: quantize this warp's query rows (per-row scale) to s8 fragments ----
    // q[mt][h][m]: row = rbase + 16*mt + 8*h + g, bytes k[16m + 4t .. +3]
    unsigned q[2][2][8];
    float sq[2][2];
    {
        const int rbase = (qg * G_Q + w) * TQ;
        #pragma unroll
        for (int mt = 0; mt < 2; mt++) {
            #pragma unroll
            for (int h = 0; h < 2; h++) {
                const int row = rbase + mt * 16 + h * 8 + g;
                const float4* rp = reinterpret_cast<const float4*>(qs + (size_t)row * DIM) + t;
                float4 v[8];
                float mx = 0.f;
                #pragma unroll
                for (int m = 0; m < 8; m++) {
                    v[m] = rp[4 * m];
                    mx = fmaxf(mx, fmaxf(fmaxf(fabsf(v[m].x), fabsf(v[m].y)),
                                         fmaxf(fabsf(v[m].z), fabsf(v[m].w))));
                }
                mx = fmaxf(mx, __shfl_xor_sync(0xffffffffu, mx, 1));
                mx = fmaxf(mx, __shfl_xor_sync(0xffffffffu, mx, 2));
                const float qm = 127.0f / mx;
                sq[mt][h] = mx * (1.0f / 127.0f);
                #pragma unroll
                for (int m = 0; m < 8; m++) {
                    int i0 = __float2int_rn(v[m].x * qm);
                    int i1 = __float2int_rn(v[m].y * qm);
                    int i2 = __float2int_rn(v[m].z * qm);
                    int i3 = __float2int_rn(v[m].w * qm);
                    q[mt][h][m] = (i0 & 0xFF) | ((i1 & 0xFF) << 8) |
                                  ((i2 & 0xFF) << 16) | ((unsigned)(i3 & 0xFF) << 24);
                }
            }
        }
    }

    // float running maxes: [mt][rh]  rows {g, g+8} of tile mt (cols folded)
    float frun[2][2] = {{-1e30f, -1e30f}, {-1e30f, -1e30f}};

    const float* spd = sp_scale + c_doc * NGRP;
    const int rl = lane & 7;              // B: token row within 8
    const int mq = lane >> 3;             // B: matrix select (k-chunk)

    #pragma unroll 1
    for (int ch = 0; ch < NCHUNK; ch++) {
        asm volatile("cp.async.wait_group 0;\n");
        __syncthreads();

        if (ch + 1 < NCHUNK) {
            const uint4* gs2  = gsrc + (size_t)(ch + 1) * SN * ROWB / 16;
            uint32_t     dbuf = sb + ((ch + 1) & 1) * BUFB;
            #pragma unroll
            for (int j = 0; j < 8; j++) {
                int f = j * THREADS + tid;
                int r = f >> 3, u = f & 7;
                uint32_t dst = dbuf + r * ROWB + ((u ^ (r & 7)) << 4);
                asm volatile("cp.async.cg.shared.global [%0], [%1], 16;\n" :: "r"(dst), "l"(gs2 + f));
            }
            asm volatile("cp.async.commit_group;\n");
        }

        const uint32_t cb = sb + (ch & 1) * BUFB;
        #pragma unroll
        for (int hf = 0; hf < 2; hf++) {  // 64-token scale halves
            int irun[2][2] = {{INT_MIN, INT_MIN}, {INT_MIN, INT_MIN}};
            #pragma unroll
            for (int nf = 0; nf < 8; nf++) {
                const int tok = hf * 64 + nf * 8 + rl;
                const uint32_t rowa = cb + tok * ROWB;
                uint32_t B0[4], B1[4];
                uint32_t a0 = rowa + ((mq ^ rl) << 4);          // kc 0..3
                uint32_t a1 = rowa + (((mq + 4) ^ rl) << 4);    // kc 4..7
                asm volatile("ldmatrix.sync.aligned.m8n8.x4.shared.b16 {%0,%1,%2,%3}, [%4];\n"
                             : "=r"(B0[0]), "=r"(B0[1]), "=r"(B0[2]), "=r"(B0[3]) : "r"(a0));
                asm volatile("ldmatrix.sync.aligned.m8n8.x4.shared.b16 {%0,%1,%2,%3}, [%4];\n"
                             : "=r"(B1[0]), "=r"(B1[1]), "=r"(B1[2]), "=r"(B1[3]) : "r"(a1));
                int c0[4] = {0, 0, 0, 0};
                int c1[4] = {0, 0, 0, 0};
                #pragma unroll
                for (int s = 0; s < 4; s++) {
                    unsigned b0 = (s < 2) ? B0[2 * s]     : B1[2 * s - 4];
                    unsigned b1 = (s < 2) ? B0[2 * s + 1] : B1[2 * s - 3];
                    mma_s8(c0, q[0][0][2*s], q[0][1][2*s], q[0][0][2*s+1], q[0][1][2*s+1], b0, b1);
                    mma_s8(c1, q[1][0][2*s], q[1][1][2*s], q[1][0][2*s+1], q[1][1][2*s+1], b0, b1);
                }
                irun[0][0] = max(irun[0][0], max(c0[0], c0[1]));
                irun[0][1] = max(irun[0][1], max(c0[2], c0[3]));
                irun[1][0] = max(irun[1][0], max(c1[0], c1[1]));
                irun[1][1] = max(irun[1][1], max(c1[2], c1[3]));
            }
            const float sp = __ldg(spd + ch * 2 + hf);
            frun[0][0] = fmaxf(frun[0][0], (float)irun[0][0] * sp);
            frun[0][1] = fmaxf(frun[0][1], (float)irun[0][1] * sp);
            frun[1][0] = fmaxf(frun[1][0], (float)irun[1][0] * sp);
            frun[1][1] = fmaxf(frun[1][1], (float)irun[1][1] * sp);
        }
    }

    // ---- apply per-row q scales, finish maxes across t lanes, sum rows ----
    float m00 = frun[0][0] * sq[0][0];    // row g
    float m01 = frun[0][1] * sq[0][1];    // row g+8
    float m10 = frun[1][0] * sq[1][0];    // row g+16
    float m11 = frun[1][1] * sq[1][1];    // row g+24
    #pragma unroll
    for (int off = 1; off <= 2; off <<= 1) {
        m00 = fmaxf(m00, __shfl_xor_sync(0xffffffffu, m00, off));
        m01 = fmaxf(m01, __shfl_xor_sync(0xffffffffu, m01, off));
        m10 = fmaxf(m10, __shfl_xor_sync(0xffffffffu, m10, off));
        m11 = fmaxf(m11, __shfl_xor_sync(0xffffffffu, m11, off));
    }
    float v = m00 + m01 + m10 + m11;      // rows {g, g+8, g+16, g+24}
    v += __shfl_xor_sync(0xffffffffu, v, 4);
    v += __shfl_xor_sync(0xffffffffu, v, 8);
    v += __shfl_xor_sync(0xffffffffu, v, 16);

    if (lane == 0) {
        out[(qg * G_Q + w) * ND + c_doc] = v;
    }
}

extern "C" void kernel_launch(void* const* d_in, const int* in_sizes, int n_in,
                              void* d_out, int out_size) {
    const float* qs = (const float*)d_in[0];   // 64*32*128
    const float* ps = (const float*)d_in[1];   // 64*1024*128
    float* out = (float*)d_out;                // 64*64

    quant_ps_kernel<<<ND * NGRP, 256>>>((const float4*)ps);

    dim3 grid(ND, NQ / G_Q);                   // (64 docs, 16 query groups)
    colbert_kernel<<<grid, THREADS>>>(qs, out);
}

// round 12
// speedup vs baseline: 2.8425x; 2.8425x over previous
#include <cuda_runtime.h>
#include <cuda_fp16.h>
#include <cstdint>

// ColBERT MaxSim on GB300 (sm_103): R4 core with fp32->f16 conversion FUSED into
// the main kernel (each CTA converts one chunk of its doc, publishes via flag,
// consumes chunks in rotated order). One launch total.
// qs: (64, 32, 128) fp32 ; ps: (64, 1024, 128) fp32 ; out: (64, 64) fp32

#define NQ       64
#define TQ       32
#define ND       64
#define TS       1024
#define DIM      128
#define G_Q      4                    // queries per CTA (1 per warp)
#define THREADS  128
#define SN       64                   // doc tokens per chunk
#define NCHUNK   (TS / SN)            // 16
#define ROWB     256                  // bytes per token row in smem (128 f16)
#define BUFB     (SN * ROWB)          // 16 KB per buffer
#define U_TOK    (DIM / 8)            // uint4 per token row (f16) = 16
#define F4_TOK   (DIM / 4)            // float4 per token row (f32) = 32

// fp16 ps scratch + publish flags (device-global; allocation-free)
__device__ uint4    scratch_ps_v[(size_t)ND * TS * DIM / 8];   // 16 MB
__device__ unsigned g_flag[ND * NCHUNK];                        // zero-init once

__device__ __forceinline__ uint32_t smem_u32(const void* p) {
    uint32_t a;
    asm("{ .reg .u64 t; cvta.to.shared.u64 t, %1; cvt.u32.u64 %0, t; }" : "=r"(a) : "l"(p));
    return a;
}
__device__ __forceinline__ unsigned pack_h2(float lo, float hi) {
    __half2 h = __floats2half2_rn(lo, hi);
    return *reinterpret_cast<unsigned*>(&h);
}
__device__ __forceinline__ uint4 pack8(float4 a, float4 b) {
    uint4 o;
    o.x = pack_h2(a.x, a.y);
    o.y = pack_h2(a.z, a.w);
    o.z = pack_h2(b.x, b.y);
    o.w = pack_h2(b.z, b.w);
    return o;
}
__device__ __forceinline__ unsigned ld_acq(const unsigned* p) {
    unsigned v;
    asm volatile("ld.acquire.gpu.global.u32 %0, [%1];" : "=r"(v) : "l"(p));
    return v;
}
__device__ __forceinline__ void mma_f16(float c[4],
                                        unsigned a0, unsigned a1, unsigned a2, unsigned a3,
                                        unsigned b0, unsigned b1) {
    asm volatile(
        "mma.sync.aligned.m16n8k16.row.col.f32.f16.f16.f32 "
        "{%0,%1,%2,%3}, {%4,%5,%6,%7}, {%8,%9}, {%0,%1,%2,%3};\n"
        : "+f"(c[0]), "+f"(c[1]), "+f"(c[2]), "+f"(c[3])
        : "r"(a0), "r"(a1), "r"(a2), "r"(a3), "r"(b0), "r"(b1));
}

// Wait until chunk (doc, ch) is published; warp-local bounded spin with
// idempotent redundant-convert fallback (identical bytes -> benign race).
__device__ __forceinline__ void wait_chunk(const float4* ps4, int doc, int ch, int lane) {
    const unsigned* f = g_flag + doc * NCHUNK + ch;
    unsigned ok = 0;
    if (lane == 0) {
        int tries = 0;
        while ((ok = ld_acq(f)) == 0u && ++tries < (1 << 22)) { }
    }
    ok = __shfl_sync(0xffffffffu, ok, 0);
    if (!ok) {
        const float4* src = ps4 + ((size_t)doc * TS + (size_t)ch * SN) * F4_TOK / 32 * 32;
        uint4* dst = scratch_ps_v + ((size_t)doc * TS + (size_t)ch * SN) * U_TOK;
        const float4* s2 = ps4 + ((size_t)doc * TS + (size_t)ch * SN) * (F4_TOK / 2) * 2;
        (void)src;
        #pragma unroll 4
        for (int j = 0; j < 32; j++) {
            int idx = j * 32 + lane;               // 1024 uint4 per chunk
            float4 a = s2[2 * idx], b = s2[2 * idx + 1];
            dst[idx] = pack8(a, b);
        }
        __threadfence();
    }
}

__global__ __launch_bounds__(THREADS, 4)
void colbert_kernel(const float* __restrict__ qs, const float* __restrict__ ps,
                    float* __restrict__ out) {
    __shared__ __align__(1024) char Bs[2 * BUFB];

    const int tid   = threadIdx.x;
    const int w     = tid >> 5;          // warp = query within group
    const int lane  = tid & 31;
    const int g     = lane >> 2;
    const int t     = lane & 3;
    const int qg    = blockIdx.x;        // fast dim: 16 qg -> bid = doc*16+qg
    const int c_doc = blockIdx.y;
    const uint32_t sb = smem_u32(Bs);

    const float4* ps4 = reinterpret_cast<const float4*>(ps);

    // ---- phase 0: convert OWN chunk (chunk index = qg) fp32 -> f16, publish ----
    {
        const float4* src = ps4 + ((size_t)c_doc * TS + (size_t)qg * SN) * (F4_TOK / 2) * 2;
        uint4* dst = scratch_ps_v + ((size_t)c_doc * TS + (size_t)qg * SN) * U_TOK;
        #pragma unroll
        for (int j = 0; j < 8; j++) {
            int idx = j * THREADS + tid;           // 1024 uint4 per chunk
            float4 a = src[2 * idx], b = src[2 * idx + 1];
            dst[idx] = pack8(a, b);
        }
        __threadfence();
        __syncthreads();
        if (tid == 0) atomicExch(&g_flag[c_doc * NCHUNK + qg], 1u);
    }

    const uint4* gsrc = scratch_ps_v + (size_t)c_doc * TS * U_TOK;

    // ---- prologue: async-copy own chunk (qg) into buffer 0 (XOR-swizzled) ----
    #pragma unroll
    for (int j = 0; j < 8; j++) {
        int f = j * THREADS + tid;       // 16B unit index, 1024 per chunk
        int r = f >> 4;                  // token row (16 units per 256B row)
        int c = f & 15;
        uint32_t dst = sb + r * ROWB + ((c ^ (r & 7)) << 4);
        asm volatile("cp.async.cg.shared.global [%0], [%1], 16;\n"
                     :: "r"(dst), "l"(gsrc + (size_t)qg * SN * U_TOK + f));
    }
    asm volatile("cp.async.commit_group;\n");

    // ---- A fragments: this warp's query (32 rows x 128 dims), fp32 -> f16 ----
    unsigned Af[2][8][4];
    {
        const int rbase = (qg * G_Q + w) * TQ;
        #pragma unroll
        for (int mt = 0; mt < 2; mt++) {
            #pragma unroll
            for (int ks = 0; ks < 8; ks++) {
                const int r0 = rbase + mt * 16 + g;
                const int cc = ks * 16 + t * 2;
                const float2* p0 = reinterpret_cast<const float2*>(qs + (size_t)r0 * DIM + cc);
                const float2* p1 = reinterpret_cast<const float2*>(qs + (size_t)(r0 + 8) * DIM + cc);
                float2 v00 = p0[0];
                float2 v02 = p0[4];
                float2 v10 = p1[0];
                float2 v12 = p1[4];
                Af[mt][ks][0] = pack_h2(v00.x, v00.y);
                Af[mt][ks][1] = pack_h2(v10.x, v10.y);
                Af[mt][ks][2] = pack_h2(v02.x, v02.y);
                Af[mt][ks][3] = pack_h2(v12.x, v12.y);
            }
        }
    }

    float rmax0 = -1e30f, rmax1 = -1e30f, rmax2 = -1e30f, rmax3 = -1e30f;

    const int rl = lane & 7;             // B: row provider within 8x8 matrix
    const int mc = lane >> 3;            // B: matrix select

    // rotated chunk order: i-th iteration handles chunk (qg + i) & 15
    #pragma unroll 1
    for (int i = 0; i < NCHUNK; i++) {
        asm volatile("cp.async.wait_group 0;\n");
        __syncthreads();

        if (i + 1 < NCHUNK) {
            const int chn = (qg + i + 1) & (NCHUNK - 1);
            wait_chunk(ps4, c_doc, chn, lane);      // per-warp; no-op once published
            const uint4* gs2  = gsrc + (size_t)chn * SN * U_TOK;
            uint32_t     dbuf = sb + ((i + 1) & 1) * BUFB;
            #pragma unroll
            for (int j = 0; j < 8; j++) {
                int f = j * THREADS + tid;
                int r = f >> 4;
                int c = f & 15;
                uint32_t dst = dbuf + r * ROWB + ((c ^ (r & 7)) << 4);
                asm volatile("cp.async.cg.shared.global [%0], [%1], 16;\n" :: "r"(dst), "l"(gs2 + f));
            }
            asm volatile("cp.async.commit_group;\n");
        }

        // ---- compute on buffer i&1 ----
        const uint32_t cbase = sb + (i & 1) * BUFB + rl * ROWB;
        #pragma unroll
        for (int nf = 0; nf < 8; nf++) {
            float cA[4] = {0.f, 0.f, 0.f, 0.f};
            float cB[4] = {0.f, 0.f, 0.f, 0.f};
            #pragma unroll
            for (int kp = 0; kp < 4; kp++) {
                uint32_t addr = cbase + nf * 8 * ROWB + ((((kp << 2) | mc) ^ rl) << 4);
                uint32_t b0, b1, b2, b3;
                asm volatile("ldmatrix.sync.aligned.m8n8.x4.shared.b16 {%0,%1,%2,%3}, [%4];\n"
                             : "=r"(b0), "=r"(b1), "=r"(b2), "=r"(b3) : "r"(addr));
                mma_f16(cA, Af[0][2*kp][0],   Af[0][2*kp][1],   Af[0][2*kp][2],   Af[0][2*kp][3],   b0, b1);
                mma_f16(cB, Af[1][2*kp][0],   Af[1][2*kp][1],   Af[1][2*kp][2],   Af[1][2*kp][3],   b0, b1);
                mma_f16(cA, Af[0][2*kp+1][0], Af[0][2*kp+1][1], Af[0][2*kp+1][2], Af[0][2*kp+1][3], b2, b3);
                mma_f16(cB, Af[1][2*kp+1][0], Af[1][2*kp+1][1], Af[1][2*kp+1][2], Af[1][2*kp+1][3], b2, b3);
            }
            rmax0 = fmaxf(rmax0, fmaxf(cA[0], cA[1]));
            rmax1 = fmaxf(rmax1, fmaxf(cA[2], cA[3]));
            rmax2 = fmaxf(rmax2, fmaxf(cB[0], cB[1]));
            rmax3 = fmaxf(rmax3, fmaxf(cB[2], cB[3]));
        }
    }

    // ---- reduce: complete row maxes across the 4 lanes sharing g ----
    #pragma unroll
    for (int off = 1; off <= 2; off <<= 1) {
        rmax0 = fmaxf(rmax0, __shfl_xor_sync(0xffffffffu, rmax0, off));
        rmax1 = fmaxf(rmax1, __shfl_xor_sync(0xffffffffu, rmax1, off));
        rmax2 = fmaxf(rmax2, __shfl_xor_sync(0xffffffffu, rmax2, off));
        rmax3 = fmaxf(rmax3, __shfl_xor_sync(0xffffffffu, rmax3, off));
    }
    float v = rmax0 + rmax1 + rmax2 + rmax3;   // rows {g, g+8, g+16, g+24}
    v += __shfl_xor_sync(0xffffffffu, v, 4);
    v += __shfl_xor_sync(0xffffffffu, v, 8);
    v += __shfl_xor_sync(0xffffffffu, v, 16);

    if (lane == 0) {
        out[(qg * G_Q + w) * ND + c_doc] = v;
    }
}

extern "C" void kernel_launch(void* const* d_in, const int* in_sizes, int n_in,
                              void* d_out, int out_size) {
    const float* qs = (const float*)d_in[0];   // 64*32*128
    const float* ps = (const float*)d_in[1];   // 64*1024*128
    float* out = (float*)d_out;                // 64*64

    dim3 grid(NQ / G_Q, ND);   // x = qg (fast), y = doc -> bid = doc*16+qg linear
    colbert_kernel<<<grid, THREADS>>>(qs, ps, out);
}